// round 2
// baseline (speedup 1.0000x reference)
#include <cuda_runtime.h>
#include <cstdint>
#include <cstddef>

#define NN 50000
#define NE 1600000
#define LAYERS 3
#define FF 218
#define FFP 224
#define NBLK 196   // ceil(NN/256)

typedef unsigned long long ULL;

// ---------------- device scratch ----------------
__device__ float g_xs[NN * 256];
__device__ float g_feat[NN * 128];
__device__ float g_gat[NN * 128];
__device__ float g_ff[NN * FFP];
__device__ float g_mlp[NN * 64];
__device__ float g_el[NN * 2];
__device__ float g_er[NN * 2];
__device__ float g_alpha[NE * 2];     // per-edge (sorted) unnormalized exp weights
__device__ float g_minv[NN * 2];      // per-node 1/den per head
__device__ int   g_rowptr[NN + 1];
__device__ int   g_cursor[NN];
__device__ int   g_srcsorted[NE];
__device__ int   g_bsum[256];
__device__ int   g_boff[256];
__device__ float g_stats[512];
__device__ float g_scale[256];
__device__ float g_shift[256];

// ---------------- f32x2 helpers ----------------
__device__ __forceinline__ ULL pk2(float lo, float hi) {
    ULL r; asm("mov.b64 %0, {%1, %2};" : "=l"(r) : "f"(lo), "f"(hi)); return r;
}
__device__ __forceinline__ void upk2(ULL v, float& lo, float& hi) {
    asm("mov.b64 {%0, %1}, %2;" : "=f"(lo), "=f"(hi) : "l"(v));
}
__device__ __forceinline__ void fma2(ULL& d, ULL a, ULL b) {
    asm("fma.rn.f32x2 %0, %1, %2, %0;" : "+l"(d) : "l"(a), "l"(b));
}

// ---------------- CSR build ----------------
__global__ void hist_kernel(const int* __restrict__ dst) {
    for (int i = blockIdx.x * blockDim.x + threadIdx.x; i < NE; i += gridDim.x * blockDim.x)
        atomicAdd(&g_cursor[dst[i]], 1);
}

__global__ void scan_a_kernel() {   // grid NBLK, block 256: per-block sums
    __shared__ int s[256];
    int t = threadIdx.x;
    int i = blockIdx.x * 256 + t;
    s[t] = (i < NN) ? g_cursor[i] : 0;
    __syncthreads();
    for (int o = 128; o; o >>= 1) {
        if (t < o) s[t] += s[t + o];
        __syncthreads();
    }
    if (t == 0) g_bsum[blockIdx.x] = s[0];
}

__global__ void scan_b_kernel() {   // 1 block 256: exclusive scan of block sums
    __shared__ int s[256];
    int t = threadIdx.x;
    int v = (t < NBLK) ? g_bsum[t] : 0;
    s[t] = v;
    __syncthreads();
    for (int o = 1; o < 256; o <<= 1) {
        int u = (t >= o) ? s[t - o] : 0;
        __syncthreads();
        s[t] += u;
        __syncthreads();
    }
    if (t < NBLK) g_boff[t] = s[t] - v;
}

__global__ void scan_c_kernel() {   // grid NBLK: within-block scan + offset
    __shared__ int s[256];
    int t = threadIdx.x;
    int i = blockIdx.x * 256 + t;
    int v = (i < NN) ? g_cursor[i] : 0;
    s[t] = v;
    __syncthreads();
    for (int o = 1; o < 256; o <<= 1) {
        int u = (t >= o) ? s[t - o] : 0;
        __syncthreads();
        s[t] += u;
        __syncthreads();
    }
    int ex = g_boff[blockIdx.x] + s[t] - v;
    if (i < NN) { g_rowptr[i] = ex; g_cursor[i] = ex; }
    if (i == NN - 1) g_rowptr[NN] = ex + v;
}

__global__ void scatter_kernel(const int* __restrict__ src, const int* __restrict__ dst) {
    for (int i = blockIdx.x * blockDim.x + threadIdx.x; i < NE; i += gridDim.x * blockDim.x) {
        int p = atomicAdd(&g_cursor[dst[i]], 1);
        g_srcsorted[p] = src[i];
    }
}

// ---------------- GEMM: C = act((scale*A+shift) @ W^T + bias) ----------------
// Inner loop: 3x LDS.128 + 8x fma.f32x2, no movs (A pre-duplicated in smem).
#define KC 32
__global__ void __launch_bounds__(256) gemm_kernel(
    const float* __restrict__ A, int lda,
    const float* __restrict__ W,
    const float* __restrict__ bias,
    const float* __restrict__ scale, const float* __restrict__ shift,
    float* __restrict__ C, int ldc,
    int nrows, int J, int K, int doRelu)
{
    __shared__ float sA[KC * 132];   // duplicated: sA[k*132 + 2m] = sA[..+2m+1] = a[m][k]
    __shared__ float sW[KC * 68];    // sW[k*68 + j] = w[j][k]
    int tid = threadIdx.x;
    int tx = tid & 15;               // j-group: 4 cols
    int ty = tid >> 4;               // m-group: 4 rows
    int m0 = blockIdx.x * 64;
    int j0 = blockIdx.y * 64;
    int lr = tid & 63;               // loader row
    int kq = tid >> 6;               // loader k-octet 0..3

    ULL acc[4][2] = {};

    for (int k0 = 0; k0 < K; k0 += KC) {
        // load A chunk (duplicated)
        {
            int gm = m0 + lr;
            const float* ap = A + (size_t)gm * lda + k0 + kq * 8;
            float v[8];
            #pragma unroll
            for (int i = 0; i < 8; i++) {
                int k = k0 + kq * 8 + i;
                float x = 0.f;
                if (gm < nrows && k < K) {
                    x = ap[i];
                    if (scale) x = fmaf(scale[k], x, shift[k]);
                }
                v[i] = x;
            }
            #pragma unroll
            for (int i = 0; i < 8; i++)
                *(ULL*)&sA[(kq * 8 + i) * 132 + 2 * lr] = pk2(v[i], v[i]);
        }
        // load W chunk
        {
            int gj = j0 + lr;
            const float* wp = W + (size_t)gj * K + k0 + kq * 8;
            #pragma unroll
            for (int i = 0; i < 8; i++) {
                int k = k0 + kq * 8 + i;
                float x = 0.f;
                if (gj < J && k < K) x = wp[i];
                sW[(kq * 8 + i) * 68 + lr] = x;
            }
        }
        __syncthreads();
        #pragma unroll
        for (int k = 0; k < KC; k++) {
            const ULL* ap = (const ULL*)&sA[k * 132 + ty * 8];
            ULL a0 = ap[0], a1 = ap[1], a2 = ap[2], a3 = ap[3];
            const ULL* bp = (const ULL*)&sW[k * 68 + tx * 4];
            ULL b0 = bp[0], b1 = bp[1];
            fma2(acc[0][0], a0, b0); fma2(acc[0][1], a0, b1);
            fma2(acc[1][0], a1, b0); fma2(acc[1][1], a1, b1);
            fma2(acc[2][0], a2, b0); fma2(acc[2][1], a2, b1);
            fma2(acc[3][0], a3, b0); fma2(acc[3][1], a3, b1);
        }
        __syncthreads();
    }
    // epilogue: thread owns rows m0+4ty+mi, cols j0+4tx+ji
    #pragma unroll
    for (int mi = 0; mi < 4; mi++) {
        int gm = m0 + ty * 4 + mi;
        float o[4];
        upk2(acc[mi][0], o[0], o[1]);
        upk2(acc[mi][1], o[2], o[3]);
        #pragma unroll
        for (int ji = 0; ji < 4; ji++) {
            int gj = j0 + tx * 4 + ji;
            if (gm < nrows && gj < J) {
                float v = o[ji] + (bias ? bias[gj] : 0.f);
                if (doRelu) v = fmaxf(v, 0.f);
                C[(size_t)gm * ldc + gj] = v;
            }
        }
    }
}

// ---------------- el / er ----------------
__global__ void __launch_bounds__(256) elr_kernel(const float* __restrict__ al,
                                                  const float* __restrict__ ar)
{
    int warp = (blockIdx.x * blockDim.x + threadIdx.x) >> 5;
    int lane = threadIdx.x & 31;
    if (warp >= NN) return;
    const float* f = g_feat + (size_t)warp * 128;
    float f0 = f[lane], f1 = f[lane + 32], f2 = f[lane + 64], f3 = f[lane + 96];
    float el0 = f0 * al[lane] + f1 * al[lane + 32];
    float el1 = f2 * al[lane + 64] + f3 * al[lane + 96];
    float er0 = f0 * ar[lane] + f1 * ar[lane + 32];
    float er1 = f2 * ar[lane + 64] + f3 * ar[lane + 96];
    #pragma unroll
    for (int o = 16; o; o >>= 1) {
        el0 += __shfl_xor_sync(~0u, el0, o);
        el1 += __shfl_xor_sync(~0u, el1, o);
        er0 += __shfl_xor_sync(~0u, er0, o);
        er1 += __shfl_xor_sync(~0u, er1, o);
    }
    if (lane == 0) {
        g_el[2 * warp] = el0; g_el[2 * warp + 1] = el1;
        g_er[2 * warp] = er0; g_er[2 * warp + 1] = er1;
    }
}

__device__ __forceinline__ float leaky02(float x) {
    return fmaxf(x, 0.f) + 0.2f * fminf(x, 0.f);
}

// ---------------- attention weights: warp per dst node ----------------
// Pass 1: compute leaky-relu logits, stash in g_alpha, track max.
// Pass 2: exponentiate in place, accumulate denominator. 1/den -> g_minv.
__global__ void __launch_bounds__(256) attn_kernel()
{
    int n    = (blockIdx.x * blockDim.x + threadIdx.x) >> 5;
    int lane = threadIdx.x & 31;
    if (n >= NN) return;
    int beg = g_rowptr[n], deg = g_rowptr[n + 1] - beg;
    float er0 = g_er[2 * n], er1 = g_er[2 * n + 1];
    float2* alp = (float2*)g_alpha;
    const float2* el2 = (const float2*)g_el;

    float m0 = -1e30f, m1 = -1e30f;
    for (int i = lane; i < deg; i += 32) {
        int s = g_srcsorted[beg + i];
        float2 el = el2[s];
        float e0 = leaky02(el.x + er0);
        float e1 = leaky02(el.y + er1);
        alp[beg + i] = make_float2(e0, e1);
        m0 = fmaxf(m0, e0); m1 = fmaxf(m1, e1);
    }
    #pragma unroll
    for (int o = 16; o; o >>= 1) {
        m0 = fmaxf(m0, __shfl_xor_sync(~0u, m0, o));
        m1 = fmaxf(m1, __shfl_xor_sync(~0u, m1, o));
    }
    float d0 = 0.f, d1 = 0.f;
    for (int i = lane; i < deg; i += 32) {
        float2 e = alp[beg + i];
        float x0 = __expf(e.x - m0);
        float x1 = __expf(e.y - m1);
        alp[beg + i] = make_float2(x0, x1);
        d0 += x0; d1 += x1;
    }
    #pragma unroll
    for (int o = 16; o; o >>= 1) {
        d0 += __shfl_xor_sync(~0u, d0, o);
        d1 += __shfl_xor_sync(~0u, d1, o);
    }
    if (lane == 0) {
        g_minv[2 * n]     = (d0 > 0.f) ? 1.f / d0 : 0.f;
        g_minv[2 * n + 1] = (d1 > 0.f) ? 1.f / d1 : 0.f;
    }
}

// ---------------- aggregation: warp per dst, uniform-broadcast loads ----------------
__global__ void __launch_bounds__(256) gat_agg_kernel(const float* __restrict__ gatb)
{
    int n    = (blockIdx.x * blockDim.x + threadIdx.x) >> 5;
    int lane = threadIdx.x & 31;
    if (n >= NN) return;
    int beg = g_rowptr[n], deg = g_rowptr[n + 1] - beg;
    int head = lane >> 4;
    const float4* feat4 = (const float4*)g_feat;
    const float2* alp = (const float2*)g_alpha;
    const int* srcs = g_srcsorted + beg;

    float4 acc = make_float4(0.f, 0.f, 0.f, 0.f);
    int e = 0;
    for (; e + 4 <= deg; e += 4) {
        #pragma unroll
        for (int j = 0; j < 4; j++) {
            int s = __ldg(&srcs[e + j]);
            float2 a2 = __ldg(&alp[beg + e + j]);
            float w = head ? a2.y : a2.x;
            float4 f = feat4[(size_t)s * 32 + lane];
            acc.x = fmaf(w, f.x, acc.x);
            acc.y = fmaf(w, f.y, acc.y);
            acc.z = fmaf(w, f.z, acc.z);
            acc.w = fmaf(w, f.w, acc.w);
        }
    }
    for (; e < deg; e++) {
        int s = __ldg(&srcs[e]);
        float2 a2 = __ldg(&alp[beg + e]);
        float w = head ? a2.y : a2.x;
        float4 f = feat4[(size_t)s * 32 + lane];
        acc.x = fmaf(w, f.x, acc.x);
        acc.y = fmaf(w, f.y, acc.y);
        acc.z = fmaf(w, f.z, acc.z);
        acc.w = fmaf(w, f.w, acc.w);
    }
    float inv = head ? g_minv[2 * n + 1] : g_minv[2 * n];
    float4 b = ((const float4*)gatb)[lane];
    acc.x = fmaf(acc.x, inv, b.x);
    acc.y = fmaf(acc.y, inv, b.y);
    acc.z = fmaf(acc.z, inv, b.z);
    acc.w = fmaf(acc.w, inv, b.w);
    ((float4*)g_gat)[(size_t)n * 32 + lane] = acc;
}

// ---------------- BN column stats (smem-reduced) ----------------
__global__ void __launch_bounds__(256) colstat_kernel(const float* __restrict__ X,
                                                      int Ccols, int nrows)
{
    __shared__ float ssum[256], ssq[256];
    int t = threadIdx.x;
    int c = t % Ccols;
    int ro = t / Ccols;
    int rpb = 256 / Ccols;
    float s = 0.f, q = 0.f;
    for (int r = blockIdx.x * rpb + ro; r < nrows; r += gridDim.x * rpb) {
        float v = X[(size_t)r * Ccols + c];
        s += v;
        q = fmaf(v, v, q);
    }
    ssum[t] = s; ssq[t] = q;
    __syncthreads();
    if (t < Ccols) {
        for (int o = 1; o < rpb; o++) {
            s += ssum[t + o * Ccols];
            q += ssq[t + o * Ccols];
        }
        atomicAdd(&g_stats[c], s);
        atomicAdd(&g_stats[256 + c], q);
    }
}

__global__ void finalize_stats_kernel(const float* __restrict__ gamma,
                                      const float* __restrict__ beta,
                                      int Ccols, float invN)
{
    int c = threadIdx.x;
    if (c < Ccols) {
        float mu  = g_stats[c] * invN;
        float var = g_stats[256 + c] * invN - mu * mu;
        float sc  = gamma[c] * rsqrtf(var + 1e-5f);
        g_scale[c] = sc;
        g_shift[c] = beta[c] - sc * mu;
    }
}

__global__ void bn_apply_kernel(int colbase)
{
    int idx = blockIdx.x * blockDim.x + threadIdx.x;
    if (idx >= NN * 64) return;
    int nrow = idx >> 6, c = idx & 63;
    g_xs[(size_t)nrow * 256 + colbase + c] = fmaf(g_scale[c], g_mlp[idx], g_shift[c]);
}

__global__ void __launch_bounds__(256) final_kernel(const float* __restrict__ w2,
                                                    float* __restrict__ out)
{
    int n    = (blockIdx.x * blockDim.x + threadIdx.x) >> 5;
    int lane = threadIdx.x & 31;
    if (n >= NN) return;
    const float* t = g_feat + (size_t)n * 64;
    float v = fmaxf(fmaf(g_scale[lane], t[lane], g_shift[lane]), 0.f) * w2[lane]
            + fmaxf(fmaf(g_scale[lane + 32], t[lane + 32], g_shift[lane + 32]), 0.f) * w2[lane + 32];
    #pragma unroll
    for (int o = 16; o; o >>= 1) v += __shfl_xor_sync(~0u, v, o);
    if (lane == 0) out[n] = v;
}

// ---------------- host driver ----------------
extern "C" void kernel_launch(void* const* d_in, const int* in_sizes, int n_in,
                              void* d_out, int out_size)
{
    const float* x       = (const float*)d_in[0];
    const int*   src     = (const int*)d_in[1];
    const int*   dst     = (const int*)d_in[2];
    const float* emb_w   = (const float*)d_in[3];
    const float* emb_b   = (const float*)d_in[4];
    const float* fc_w    = (const float*)d_in[5];
    const float* attn_l  = (const float*)d_in[6];
    const float* attn_r  = (const float*)d_in[7];
    const float* gat_b   = (const float*)d_in[8];
    const float* bn1_g   = (const float*)d_in[9];
    const float* bn1_b   = (const float*)d_in[10];
    const float* ff_w1   = (const float*)d_in[11];
    const float* ff_b1   = (const float*)d_in[12];
    const float* ff_w2   = (const float*)d_in[13];
    const float* ff_b2   = (const float*)d_in[14];
    const float* bn2_g   = (const float*)d_in[15];
    const float* bn2_b   = (const float*)d_in[16];
    const float* mlp_w1  = (const float*)d_in[17];
    const float* mlp_bn_g= (const float*)d_in[18];
    const float* mlp_bn_b= (const float*)d_in[19];
    const float* mlp_w2  = (const float*)d_in[20];
    float* out = (float*)d_out;

    void* p;
    cudaGetSymbolAddress(&p, g_cursor); int*   cur   = (int*)p;
    cudaGetSymbolAddress(&p, g_stats);  float* stats = (float*)p;
    cudaGetSymbolAddress(&p, g_xs);     float* xs    = (float*)p;
    cudaGetSymbolAddress(&p, g_feat);   float* feat  = (float*)p;
    cudaGetSymbolAddress(&p, g_gat);    float* gat   = (float*)p;
    cudaGetSymbolAddress(&p, g_ff);     float* ffb   = (float*)p;
    cudaGetSymbolAddress(&p, g_mlp);    float* mlpb  = (float*)p;
    cudaGetSymbolAddress(&p, g_scale);  float* sc    = (float*)p;
    cudaGetSymbolAddress(&p, g_shift);  float* sh    = (float*)p;

    const int GX = (NN + 63) / 64;          // 782
    const int WG = (NN * 32 + 255) / 256;   // warp-per-node grids
    const float invN = 1.f / (float)NN;

    // CSR build (by dst)
    cudaMemsetAsync(cur, 0, NN * sizeof(int));
    hist_kernel<<<2048, 256>>>(dst);
    scan_a_kernel<<<NBLK, 256>>>();
    scan_b_kernel<<<1, 256>>>();
    scan_c_kernel<<<NBLK, 256>>>();
    scatter_kernel<<<2048, 256>>>(src, dst);

    // embedding: xs[:, 0:64] = x @ emb_w^T + emb_b
    gemm_kernel<<<dim3(GX, 1), 256>>>(x, 64, emb_w, emb_b, nullptr, nullptr,
                                      xs, 256, NN, 64, 64, 0);

    for (int l = 0; l < LAYERS; l++) {
        const float* h = xs + l * 64;  // lda 256
        gemm_kernel<<<dim3(GX, 2), 256>>>(h, 256, fc_w + (size_t)l * 128 * 64,
                                          nullptr, nullptr, nullptr,
                                          feat, 128, NN, 128, 64, 0);
        elr_kernel<<<WG, 256>>>(attn_l + l * 128, attn_r + l * 128);
        attn_kernel<<<WG, 256>>>();
        gat_agg_kernel<<<WG, 256>>>(gat_b + l * 128);

        cudaMemsetAsync(stats, 0, 512 * sizeof(float));
        colstat_kernel<<<256, 256>>>(gat, 128, NN);
        finalize_stats_kernel<<<1, 128>>>(bn1_g + l * 128, bn1_b + l * 128, 128, invN);

        gemm_kernel<<<dim3(GX, 4), 256>>>(gat, 128, ff_w1 + (size_t)l * FF * 128,
                                          ff_b1 + l * FF, sc, sh,
                                          ffb, FFP, NN, FF, 128, 1);
        gemm_kernel<<<dim3(GX, 1), 256>>>(ffb, FFP, ff_w2 + (size_t)l * 64 * FF,
                                          ff_b2 + l * 64, nullptr, nullptr,
                                          mlpb, 64, NN, 64, FF, 0);

        cudaMemsetAsync(stats, 0, 512 * sizeof(float));
        colstat_kernel<<<256, 256>>>(mlpb, 64, NN);
        finalize_stats_kernel<<<1, 64>>>(bn2_g + l * 64, bn2_b + l * 64, 64, invN);
        bn_apply_kernel<<<(NN * 64 + 255) / 256, 256>>>((l + 1) * 64);
    }

    // MLP head
    gemm_kernel<<<dim3(GX, 1), 256>>>(xs, 256, mlp_w1, nullptr, nullptr, nullptr,
                                      feat, 64, NN, 64, 256, 0);
    cudaMemsetAsync(stats, 0, 512 * sizeof(float));
    colstat_kernel<<<256, 256>>>(feat, 64, NN);
    finalize_stats_kernel<<<1, 64>>>(mlp_bn_g, mlp_bn_b, 64, invN);
    final_kernel<<<WG, 256>>>(mlp_w2, out);

    (void)in_sizes; (void)n_in; (void)out_size;
}

// round 4
// speedup vs baseline: 1.7773x; 1.7773x over previous
#include <cuda_runtime.h>
#include <cstdint>
#include <cstddef>

#define NN 50000
#define NE 1600000
#define LAYERS 3
#define FF 218
#define FFP 224
#define NBLK 196   // ceil(NN/256)

typedef unsigned long long ULL;

// ---------------- device scratch ----------------
__device__ float g_xs[NN * 256];
__device__ float g_feat[NN * 128];
__device__ float g_gat[NN * 128];
__device__ float g_ff[NN * FFP];
__device__ float g_mlp[NN * 64];
__device__ float g_el[NN * 2];
__device__ float g_er[NN * 2];
__device__ float g_alpha[NE * 2];
__device__ float g_minv[NN * 2];
__device__ int   g_rowptr[NN + 1];
__device__ int   g_cursor[NN];
__device__ int   g_srcsorted[NE];
__device__ int   g_bsum[256];
__device__ int   g_boff[256];
__device__ float g_stats[512];
__device__ float g_scale[256];
__device__ float g_shift[256];

// ---------------- helpers ----------------
__device__ __forceinline__ float tf32r(float x) {
    uint32_t r;
    asm("cvt.rna.tf32.f32 %0, %1;" : "=r"(r) : "f"(x));
    return __uint_as_float(r);
}

__device__ __forceinline__ void mma_tf32(float* d, const uint32_t* a, const uint32_t* b) {
    asm volatile(
        "mma.sync.aligned.m16n8k8.row.col.f32.tf32.tf32.f32 "
        "{%0,%1,%2,%3}, {%4,%5,%6,%7}, {%8,%9}, {%0,%1,%2,%3};"
        : "+f"(d[0]), "+f"(d[1]), "+f"(d[2]), "+f"(d[3])
        : "r"(a[0]), "r"(a[1]), "r"(a[2]), "r"(a[3]), "r"(b[0]), "r"(b[1]));
}

// ---------------- CSR build ----------------
__global__ void hist_kernel(const int* __restrict__ dst) {
    for (int i = blockIdx.x * blockDim.x + threadIdx.x; i < NE; i += gridDim.x * blockDim.x)
        atomicAdd(&g_cursor[dst[i]], 1);
}

__global__ void scan_a_kernel() {
    __shared__ int s[256];
    int t = threadIdx.x;
    int i = blockIdx.x * 256 + t;
    s[t] = (i < NN) ? g_cursor[i] : 0;
    __syncthreads();
    for (int o = 128; o; o >>= 1) {
        if (t < o) s[t] += s[t + o];
        __syncthreads();
    }
    if (t == 0) g_bsum[blockIdx.x] = s[0];
}

__global__ void scan_b_kernel() {
    __shared__ int s[256];
    int t = threadIdx.x;
    int v = (t < NBLK) ? g_bsum[t] : 0;
    s[t] = v;
    __syncthreads();
    for (int o = 1; o < 256; o <<= 1) {
        int u = (t >= o) ? s[t - o] : 0;
        __syncthreads();
        s[t] += u;
        __syncthreads();
    }
    if (t < NBLK) g_boff[t] = s[t] - v;
}

__global__ void scan_c_kernel() {
    __shared__ int s[256];
    int t = threadIdx.x;
    int i = blockIdx.x * 256 + t;
    int v = (i < NN) ? g_cursor[i] : 0;
    s[t] = v;
    __syncthreads();
    for (int o = 1; o < 256; o <<= 1) {
        int u = (t >= o) ? s[t - o] : 0;
        __syncthreads();
        s[t] += u;
        __syncthreads();
    }
    int ex = g_boff[blockIdx.x] + s[t] - v;
    if (i < NN) { g_rowptr[i] = ex; g_cursor[i] = ex; }
    if (i == NN - 1) g_rowptr[NN] = ex + v;
}

__global__ void scatter_kernel(const int* __restrict__ src, const int* __restrict__ dst) {
    for (int i = blockIdx.x * blockDim.x + threadIdx.x; i < NE; i += gridDim.x * blockDim.x) {
        int p = atomicAdd(&g_cursor[dst[i]], 1);
        g_srcsorted[p] = src[i];
    }
}

// ---------------- 3xTF32 tensor-core GEMM ----------------
// C = act((scale*A+shift) @ W^T + bias). Split-precision: x = hi + lo (both tf32),
// A*B ~= Ah*Bh + Ah*Bl + Al*Bh accumulated in fp32.
// Block tile 128x64, 8 warps of 32x32, Kc=16, mma m16n8k8.
#define KC 16
#define PA 20   // sA row stride (16 + 4 pad)
#define PW 72   // sW row stride
__global__ void __launch_bounds__(256) gemm_kernel(
    const float* __restrict__ A, int lda,
    const float* __restrict__ W,
    const float* __restrict__ bias,
    const float* __restrict__ scale, const float* __restrict__ shift,
    float* __restrict__ C, int ldc,
    int nrows, int J, int K, int doRelu)
{
    __shared__ float sAh[128 * PA], sAl[128 * PA];   // [m][k]
    __shared__ float sWh[KC * PW],  sWl[KC * PW];    // [k][n]
    int tid  = threadIdx.x;
    int lane = tid & 31;
    int w    = tid >> 5;
    int mw = w >> 1, nw = w & 1;
    int mB = mw * 32, nB = nw * 32;
    int qr = lane >> 2, qc = lane & 3;
    int m0 = blockIdx.x * 128;
    int j0 = blockIdx.y * 64;

    float d[2][4][4];
    #pragma unroll
    for (int a = 0; a < 2; a++)
        #pragma unroll
        for (int b = 0; b < 4; b++)
            #pragma unroll
            for (int c = 0; c < 4; c++) d[a][b][c] = 0.f;

    for (int k0 = 0; k0 < K; k0 += KC) {
        // ---- load A chunk: thread -> (m = tid>>1, kh = (tid&1)*8), 8 floats
        {
            int m  = tid >> 1;
            int kh = (tid & 1) * 8;
            int gm = m0 + m;
            const float* ap = A + (size_t)gm * lda + k0 + kh;
            #pragma unroll
            for (int v = 0; v < 2; v++) {
                int kb = k0 + kh + v * 4;
                float t0 = 0.f, t1 = 0.f, t2 = 0.f, t3 = 0.f;
                if (gm < nrows) {
                    if (kb + 4 <= K) {
                        float4 x = *(const float4*)(ap + v * 4);
                        t0 = x.x; t1 = x.y; t2 = x.z; t3 = x.w;
                    } else {
                        if (kb     < K) t0 = ap[v * 4];
                        if (kb + 1 < K) t1 = ap[v * 4 + 1];
                        if (kb + 2 < K) t2 = ap[v * 4 + 2];
                        if (kb + 3 < K) t3 = ap[v * 4 + 3];
                    }
                    if (scale) {
                        if (kb     < K) t0 = fmaf(scale[kb],     t0, shift[kb]);
                        if (kb + 1 < K) t1 = fmaf(scale[kb + 1], t1, shift[kb + 1]);
                        if (kb + 2 < K) t2 = fmaf(scale[kb + 2], t2, shift[kb + 2]);
                        if (kb + 3 < K) t3 = fmaf(scale[kb + 3], t3, shift[kb + 3]);
                    }
                }
                float4 hi, lo;
                hi.x = tf32r(t0); lo.x = tf32r(t0 - hi.x);
                hi.y = tf32r(t1); lo.y = tf32r(t1 - hi.y);
                hi.z = tf32r(t2); lo.z = tf32r(t2 - hi.z);
                hi.w = tf32r(t3); lo.w = tf32r(t3 - hi.w);
                *(float4*)&sAh[m * PA + kh + v * 4] = hi;
                *(float4*)&sAl[m * PA + kh + v * 4] = lo;
            }
        }
        // ---- load W chunk: thread -> (n = tid&63, kq = (tid>>6)*4), 4 floats
        {
            int n  = tid & 63;
            int kq = (tid >> 6) * 4;
            int gj = j0 + n;
            const float* wp = W + (size_t)gj * K + k0 + kq;
            #pragma unroll
            for (int i = 0; i < 4; i++) {
                int k = k0 + kq + i;
                float x = (gj < J && k < K) ? wp[i] : 0.f;
                float hi = tf32r(x);
                sWh[(kq + i) * PW + n] = hi;
                sWl[(kq + i) * PW + n] = tf32r(x - hi);
            }
        }
        __syncthreads();
        #pragma unroll
        for (int kk = 0; kk < KC; kk += 8) {
            uint32_t ah[2][4], al[2][4], bh[4][2], bl[4][2];
            #pragma unroll
            for (int mi = 0; mi < 2; mi++) {
                int r = mB + mi * 16 + qr;
                ah[mi][0] = __float_as_uint(sAh[r * PA + kk + qc]);
                ah[mi][1] = __float_as_uint(sAh[(r + 8) * PA + kk + qc]);
                ah[mi][2] = __float_as_uint(sAh[r * PA + kk + 4 + qc]);
                ah[mi][3] = __float_as_uint(sAh[(r + 8) * PA + kk + 4 + qc]);
                al[mi][0] = __float_as_uint(sAl[r * PA + kk + qc]);
                al[mi][1] = __float_as_uint(sAl[(r + 8) * PA + kk + qc]);
                al[mi][2] = __float_as_uint(sAl[r * PA + kk + 4 + qc]);
                al[mi][3] = __float_as_uint(sAl[(r + 8) * PA + kk + 4 + qc]);
            }
            #pragma unroll
            for (int nj = 0; nj < 4; nj++) {
                int c = nB + nj * 8 + qr;
                bh[nj][0] = __float_as_uint(sWh[(kk + qc) * PW + c]);
                bh[nj][1] = __float_as_uint(sWh[(kk + 4 + qc) * PW + c]);
                bl[nj][0] = __float_as_uint(sWl[(kk + qc) * PW + c]);
                bl[nj][1] = __float_as_uint(sWl[(kk + 4 + qc) * PW + c]);
            }
            #pragma unroll
            for (int mi = 0; mi < 2; mi++)
                #pragma unroll
                for (int nj = 0; nj < 4; nj++) {
                    mma_tf32(d[mi][nj], ah[mi], bh[nj]);
                    mma_tf32(d[mi][nj], ah[mi], bl[nj]);
                    mma_tf32(d[mi][nj], al[mi], bh[nj]);
                }
        }
        __syncthreads();
    }

    // ---- epilogue
    #pragma unroll
    for (int mi = 0; mi < 2; mi++) {
        #pragma unroll
        for (int nj = 0; nj < 4; nj++) {
            int c0 = j0 + nB + nj * 8 + qc * 2;
            float b0 = 0.f, b1 = 0.f;
            if (bias) {
                if (c0     < J) b0 = bias[c0];
                if (c0 + 1 < J) b1 = bias[c0 + 1];
            }
            #pragma unroll
            for (int h = 0; h < 2; h++) {
                int r = m0 + mB + mi * 16 + qr + h * 8;
                if (r < nrows) {
                    float v0 = d[mi][nj][2 * h]     + b0;
                    float v1 = d[mi][nj][2 * h + 1] + b1;
                    if (doRelu) { v0 = fmaxf(v0, 0.f); v1 = fmaxf(v1, 0.f); }
                    if (c0 + 1 < J) {
                        *(float2*)&C[(size_t)r * ldc + c0] = make_float2(v0, v1);
                    } else if (c0 < J) {
                        C[(size_t)r * ldc + c0] = v0;
                    }
                }
            }
        }
    }
}

// ---------------- el / er ----------------
__global__ void __launch_bounds__(256) elr_kernel(const float* __restrict__ al,
                                                  const float* __restrict__ ar)
{
    int warp = (blockIdx.x * blockDim.x + threadIdx.x) >> 5;
    int lane = threadIdx.x & 31;
    if (warp >= NN) return;
    const float* f = g_feat + (size_t)warp * 128;
    float f0 = f[lane], f1 = f[lane + 32], f2 = f[lane + 64], f3 = f[lane + 96];
    float el0 = f0 * al[lane] + f1 * al[lane + 32];
    float el1 = f2 * al[lane + 64] + f3 * al[lane + 96];
    float er0 = f0 * ar[lane] + f1 * ar[lane + 32];
    float er1 = f2 * ar[lane + 64] + f3 * ar[lane + 96];
    #pragma unroll
    for (int o = 16; o; o >>= 1) {
        el0 += __shfl_xor_sync(~0u, el0, o);
        el1 += __shfl_xor_sync(~0u, el1, o);
        er0 += __shfl_xor_sync(~0u, er0, o);
        er1 += __shfl_xor_sync(~0u, er1, o);
    }
    if (lane == 0) {
        g_el[2 * warp] = el0; g_el[2 * warp + 1] = el1;
        g_er[2 * warp] = er0; g_er[2 * warp + 1] = er1;
    }
}

__device__ __forceinline__ float leaky02(float x) {
    return fmaxf(x, 0.f) + 0.2f * fminf(x, 0.f);
}

// ---------------- attention weights ----------------
__global__ void __launch_bounds__(256) attn_kernel()
{
    int n    = (blockIdx.x * blockDim.x + threadIdx.x) >> 5;
    int lane = threadIdx.x & 31;
    if (n >= NN) return;
    int beg = g_rowptr[n], deg = g_rowptr[n + 1] - beg;
    float er0 = g_er[2 * n], er1 = g_er[2 * n + 1];
    float2* alp = (float2*)g_alpha;
    const float2* el2 = (const float2*)g_el;

    float m0 = -1e30f, m1 = -1e30f;
    for (int i = lane; i < deg; i += 32) {
        int s = g_srcsorted[beg + i];
        float2 el = el2[s];
        float e0 = leaky02(el.x + er0);
        float e1 = leaky02(el.y + er1);
        alp[beg + i] = make_float2(e0, e1);
        m0 = fmaxf(m0, e0); m1 = fmaxf(m1, e1);
    }
    #pragma unroll
    for (int o = 16; o; o >>= 1) {
        m0 = fmaxf(m0, __shfl_xor_sync(~0u, m0, o));
        m1 = fmaxf(m1, __shfl_xor_sync(~0u, m1, o));
    }
    float d0 = 0.f, d1 = 0.f;
    for (int i = lane; i < deg; i += 32) {
        float2 e = alp[beg + i];
        float x0 = __expf(e.x - m0);
        float x1 = __expf(e.y - m1);
        alp[beg + i] = make_float2(x0, x1);
        d0 += x0; d1 += x1;
    }
    #pragma unroll
    for (int o = 16; o; o >>= 1) {
        d0 += __shfl_xor_sync(~0u, d0, o);
        d1 += __shfl_xor_sync(~0u, d1, o);
    }
    if (lane == 0) {
        g_minv[2 * n]     = (d0 > 0.f) ? 1.f / d0 : 0.f;
        g_minv[2 * n + 1] = (d1 > 0.f) ? 1.f / d1 : 0.f;
    }
}

// ---------------- aggregation ----------------
__global__ void __launch_bounds__(256) gat_agg_kernel(const float* __restrict__ gatb)
{
    int n    = (blockIdx.x * blockDim.x + threadIdx.x) >> 5;
    int lane = threadIdx.x & 31;
    if (n >= NN) return;
    int beg = g_rowptr[n], deg = g_rowptr[n + 1] - beg;
    int head = lane >> 4;
    const float4* feat4 = (const float4*)g_feat;
    const float2* alp = (const float2*)g_alpha;
    const int* srcs = g_srcsorted + beg;

    float4 acc = make_float4(0.f, 0.f, 0.f, 0.f);
    int e = 0;
    for (; e + 4 <= deg; e += 4) {
        #pragma unroll
        for (int j = 0; j < 4; j++) {
            int s = __ldg(&srcs[e + j]);
            float2 a2 = __ldg(&alp[beg + e + j]);
            float wgt = head ? a2.y : a2.x;
            float4 f = feat4[(size_t)s * 32 + lane];
            acc.x = fmaf(wgt, f.x, acc.x);
            acc.y = fmaf(wgt, f.y, acc.y);
            acc.z = fmaf(wgt, f.z, acc.z);
            acc.w = fmaf(wgt, f.w, acc.w);
        }
    }
    for (; e < deg; e++) {
        int s = __ldg(&srcs[e]);
        float2 a2 = __ldg(&alp[beg + e]);
        float wgt = head ? a2.y : a2.x;
        float4 f = feat4[(size_t)s * 32 + lane];
        acc.x = fmaf(wgt, f.x, acc.x);
        acc.y = fmaf(wgt, f.y, acc.y);
        acc.z = fmaf(wgt, f.z, acc.z);
        acc.w = fmaf(wgt, f.w, acc.w);
    }
    float inv = head ? g_minv[2 * n + 1] : g_minv[2 * n];
    float4 b = ((const float4*)gatb)[lane];
    acc.x = fmaf(acc.x, inv, b.x);
    acc.y = fmaf(acc.y, inv, b.y);
    acc.z = fmaf(acc.z, inv, b.z);
    acc.w = fmaf(acc.w, inv, b.w);
    ((float4*)g_gat)[(size_t)n * 32 + lane] = acc;
}

// ---------------- BN column stats ----------------
__global__ void __launch_bounds__(256) colstat_kernel(const float* __restrict__ X,
                                                      int Ccols, int nrows)
{
    __shared__ float ssum[256], ssq[256];
    int t = threadIdx.x;
    int c = t % Ccols;
    int ro = t / Ccols;
    int rpb = 256 / Ccols;
    float s = 0.f, q = 0.f;
    for (int r = blockIdx.x * rpb + ro; r < nrows; r += gridDim.x * rpb) {
        float v = X[(size_t)r * Ccols + c];
        s += v;
        q = fmaf(v, v, q);
    }
    ssum[t] = s; ssq[t] = q;
    __syncthreads();
    if (t < Ccols) {
        for (int o = 1; o < rpb; o++) {
            s += ssum[t + o * Ccols];
            q += ssq[t + o * Ccols];
        }
        atomicAdd(&g_stats[c], s);
        atomicAdd(&g_stats[256 + c], q);
    }
}

__global__ void finalize_stats_kernel(const float* __restrict__ gamma,
                                      const float* __restrict__ beta,
                                      int Ccols, float invN)
{
    int c = threadIdx.x;
    if (c < Ccols) {
        float mu  = g_stats[c] * invN;
        float var = g_stats[256 + c] * invN - mu * mu;
        float sc  = gamma[c] * rsqrtf(var + 1e-5f);
        g_scale[c] = sc;
        g_shift[c] = beta[c] - sc * mu;
    }
}

__global__ void bn_apply_kernel(int colbase)
{
    int idx = blockIdx.x * blockDim.x + threadIdx.x;
    if (idx >= NN * 64) return;
    int nrow = idx >> 6, c = idx & 63;
    g_xs[(size_t)nrow * 256 + colbase + c] = fmaf(g_scale[c], g_mlp[idx], g_shift[c]);
}

__global__ void __launch_bounds__(256) final_kernel(const float* __restrict__ w2,
                                                    float* __restrict__ out)
{
    int n    = (blockIdx.x * blockDim.x + threadIdx.x) >> 5;
    int lane = threadIdx.x & 31;
    if (n >= NN) return;
    const float* t = g_feat + (size_t)n * 64;
    float v = fmaxf(fmaf(g_scale[lane], t[lane], g_shift[lane]), 0.f) * w2[lane]
            + fmaxf(fmaf(g_scale[lane + 32], t[lane + 32], g_shift[lane + 32]), 0.f) * w2[lane + 32];
    #pragma unroll
    for (int o = 16; o; o >>= 1) v += __shfl_xor_sync(~0u, v, o);
    if (lane == 0) out[n] = v;
}

// ---------------- host driver ----------------
extern "C" void kernel_launch(void* const* d_in, const int* in_sizes, int n_in,
                              void* d_out, int out_size)
{
    const float* x       = (const float*)d_in[0];
    const int*   src     = (const int*)d_in[1];
    const int*   dst     = (const int*)d_in[2];
    const float* emb_w   = (const float*)d_in[3];
    const float* emb_b   = (const float*)d_in[4];
    const float* fc_w    = (const float*)d_in[5];
    const float* attn_l  = (const float*)d_in[6];
    const float* attn_r  = (const float*)d_in[7];
    const float* gat_b   = (const float*)d_in[8];
    const float* bn1_g   = (const float*)d_in[9];
    const float* bn1_b   = (const float*)d_in[10];
    const float* ff_w1   = (const float*)d_in[11];
    const float* ff_b1   = (const float*)d_in[12];
    const float* ff_w2   = (const float*)d_in[13];
    const float* ff_b2   = (const float*)d_in[14];
    const float* bn2_g   = (const float*)d_in[15];
    const float* bn2_b   = (const float*)d_in[16];
    const float* mlp_w1  = (const float*)d_in[17];
    const float* mlp_bn_g= (const float*)d_in[18];
    const float* mlp_bn_b= (const float*)d_in[19];
    const float* mlp_w2  = (const float*)d_in[20];
    float* out = (float*)d_out;

    void* p;
    cudaGetSymbolAddress(&p, g_cursor); int*   cur   = (int*)p;
    cudaGetSymbolAddress(&p, g_stats);  float* stats = (float*)p;
    cudaGetSymbolAddress(&p, g_xs);     float* xs    = (float*)p;
    cudaGetSymbolAddress(&p, g_feat);   float* feat  = (float*)p;
    cudaGetSymbolAddress(&p, g_gat);    float* gat   = (float*)p;
    cudaGetSymbolAddress(&p, g_ff);     float* ffb   = (float*)p;
    cudaGetSymbolAddress(&p, g_mlp);    float* mlpb  = (float*)p;
    cudaGetSymbolAddress(&p, g_scale);  float* sc    = (float*)p;
    cudaGetSymbolAddress(&p, g_shift);  float* sh    = (float*)p;

    const int GX = (NN + 127) / 128;        // 391 (M tile 128)
    const int WG = (NN * 32 + 255) / 256;
    const float invN = 1.f / (float)NN;

    // CSR build; emb GEMM placed as launch #5 (ncu profiles launch 5)
    cudaMemsetAsync(cur, 0, NN * sizeof(int));                       // 1
    hist_kernel<<<2048, 256>>>(dst);                                 // 2
    scan_a_kernel<<<NBLK, 256>>>();                                  // 3
    scan_b_kernel<<<1, 256>>>();                                     // 4
    gemm_kernel<<<dim3(GX, 1), 256>>>(x, 64, emb_w, emb_b,           // 5 (profiled)
                                      nullptr, nullptr,
                                      xs, 256, NN, 64, 64, 0);
    scan_c_kernel<<<NBLK, 256>>>();                                  // 6
    scatter_kernel<<<2048, 256>>>(src, dst);                         // 7

    for (int l = 0; l < LAYERS; l++) {
        const float* h = xs + l * 64;  // lda 256
        gemm_kernel<<<dim3(GX, 2), 256>>>(h, 256, fc_w + (size_t)l * 128 * 64,
                                          nullptr, nullptr, nullptr,
                                          feat, 128, NN, 128, 64, 0);
        elr_kernel<<<WG, 256>>>(attn_l + l * 128, attn_r + l * 128);
        attn_kernel<<<WG, 256>>>();
        gat_agg_kernel<<<WG, 256>>>(gat_b + l * 128);

        cudaMemsetAsync(stats, 0, 512 * sizeof(float));
        colstat_kernel<<<256, 256>>>(gat, 128, NN);
        finalize_stats_kernel<<<1, 128>>>(bn1_g + l * 128, bn1_b + l * 128, 128, invN);

        gemm_kernel<<<dim3(GX, 4), 256>>>(gat, 128, ff_w1 + (size_t)l * FF * 128,
                                          ff_b1 + l * FF, sc, sh,
                                          ffb, FFP, NN, FF, 128, 1);
        gemm_kernel<<<dim3(GX, 1), 256>>>(ffb, FFP, ff_w2 + (size_t)l * 64 * FF,
                                          ff_b2 + l * 64, nullptr, nullptr,
                                          mlpb, 64, NN, 64, FF, 0);

        cudaMemsetAsync(stats, 0, 512 * sizeof(float));
        colstat_kernel<<<256, 256>>>(mlpb, 64, NN);
        finalize_stats_kernel<<<1, 64>>>(bn2_g + l * 64, bn2_b + l * 64, 64, invN);
        bn_apply_kernel<<<(NN * 64 + 255) / 256, 256>>>((l + 1) * 64);
    }

    // MLP head
    gemm_kernel<<<dim3(GX, 1), 256>>>(xs, 256, mlp_w1, nullptr, nullptr, nullptr,
                                      feat, 64, NN, 64, 256, 0);
    cudaMemsetAsync(stats, 0, 512 * sizeof(float));
    colstat_kernel<<<256, 256>>>(feat, 64, NN);
    finalize_stats_kernel<<<1, 64>>>(mlp_bn_g, mlp_bn_b, 64, invN);
    final_kernel<<<WG, 256>>>(mlp_w2, out);

    (void)in_sizes; (void)n_in; (void)out_size;
}